// round 4
// baseline (speedup 1.0000x reference)
#include <cuda_runtime.h>
#include <cstddef>

#define BB 16384
#define MM 256
#define GG 50
#define HH 8
#define CC 70

#define TB 32              // cells per block
#define MC 8               // modules per chunk
#define NCH (MM / MC)      // 32 chunks
#define NT 128             // threads per block
#define XS_STRIDE 404      // 400 floats + 4 pad (16B aligned, reduces LDS conflicts)

// shared layout (in floats)
#define OFF_XS   0
#define SZ_XS    (TB * XS_STRIDE)            // 12928
#define OFF_W1   (OFF_XS + SZ_XS)
#define SZ_W1    (MC * GG * HH)              // 3200
#define OFF_W2   (OFF_W1 + SZ_W1)
#define SZ_W2    (MC * HH)                   // 64
#define OFF_B2   (OFF_W2 + SZ_W2)
#define SZ_B2    MC                          // 8
#define OFF_MS   (OFF_B2 + SZ_B2)
#define SZ_MS    (MC * (TB + 1))             // 264
#define OFF_CMS  (OFF_MS + SZ_MS)
#define SZ_CMS   (CC * MC)                   // 560
#define SMEM_FLOATS (OFF_CMS + SZ_CMS + 8)
#define SMEM_BYTES  (SMEM_FLOATS * 4)

__device__ __forceinline__ float tshrink(float v) { return v - tanhf(v); }

__device__ __forceinline__ void fma8(float acc[HH], float xv, float4 w0, float4 w1) {
    acc[0] += xv * w0.x; acc[1] += xv * w0.y; acc[2] += xv * w0.z; acc[3] += xv * w0.w;
    acc[4] += xv * w1.x; acc[5] += xv * w1.y; acc[6] += xv * w1.z; acc[7] += xv * w1.w;
}

__global__ void __launch_bounds__(NT) flux_fused_kernel(
    const float* __restrict__ x,    // [B, M*G]
    const float* __restrict__ W1,   // [M, G, H]
    const float* __restrict__ W2,   // [M, H]
    const float* __restrict__ b2,   // [M]
    const float* __restrict__ cm,   // [C, M]
    float* __restrict__ out_m,      // [B, M]
    float* __restrict__ out_c)      // [B, C]
{
    extern __shared__ float sm[];
    float* xs  = sm + OFF_XS;    // [TB][XS_STRIDE]
    float* w1s = sm + OFF_W1;    // [MC][GG][HH]
    float* w2s = sm + OFF_W2;    // [MC][HH]
    float* b2s = sm + OFF_B2;    // [MC]
    float* ms  = sm + OFF_MS;    // [MC][TB+1]  (m chunk, mod-major)
    float* cms = sm + OFF_CMS;   // [CC][MC]

    const int tid      = threadIdx.x;
    const int cellBase = blockIdx.x * TB;

    // compute-phase mapping: 2 cells per thread, one module
    const int mod = tid >> 4;        // 0..7
    const int cA  = tid & 15;        // 0..15
    const int cB  = cA + 16;         // 16..31

    // c-phase mapping
    const int ccell = tid & (TB - 1);   // 0..31 (lane = cell -> conflict-free, uniform comp)
    const int cset  = tid >> 5;         // 0..3, each owns 18 comps (4*18=72 >= 70)

    float cacc[18];
#pragma unroll
    for (int j = 0; j < 18; j++) cacc[j] = 0.f;

    for (int ch = 0; ch < NCH; ch++) {
        const int modBase = ch * MC;

        // ---- stage x tile: 32 cells x 400 floats, fully coalesced float4 ----
#pragma unroll
        for (int i = tid; i < TB * 100; i += NT) {
            const int cell = i / 100;
            const int c4   = i % 100;
            float4 v = *(const float4*)(x + (size_t)(cellBase + cell) * (MM * GG)
                                          + (size_t)modBase * GG + c4 * 4);
            *(float4*)(xs + cell * XS_STRIDE + c4 * 4) = v;
        }
        // ---- stage W1 chunk: contiguous 3200 floats ----
        {
            const float4* wg  = (const float4*)(W1 + (size_t)modBase * GG * HH);
            float4*       wsd = (float4*)w1s;
#pragma unroll
            for (int i = tid; i < (MC * GG * HH) / 4; i += NT) wsd[i] = wg[i];
        }
        // ---- stage W2 / b2 / cm chunk ----
        if (tid < MC * HH) w2s[tid] = W2[(size_t)modBase * HH + tid];
        if (tid < MC)      b2s[tid] = b2[modBase + tid];
#pragma unroll
        for (int i = tid; i < CC * MC; i += NT) {
            const int comp = i / MC;
            const int mo   = i % MC;
            cms[i] = cm[(size_t)comp * MM + modBase + mo];
        }
        __syncthreads();

        // ---- compute h[8] then m for 2 cells ----
        float accA[HH], accB[HH];
#pragma unroll
        for (int h = 0; h < HH; h++) { accA[h] = 0.f; accB[h] = 0.f; }

        const float*  xA = xs + cA * XS_STRIDE + mod * GG;
        const float*  xB = xs + cB * XS_STRIDE + mod * GG;
        const float4* wv = (const float4*)(w1s + mod * GG * HH);

#pragma unroll
        for (int g = 0; g < GG; g += 2) {
            float2 a = *(const float2*)(xA + g);
            float2 b = *(const float2*)(xB + g);
            float4 w0a = wv[2 * g + 0], w0b = wv[2 * g + 1];
            float4 w1a = wv[2 * g + 2], w1b = wv[2 * g + 3];
            fma8(accA, a.x, w0a, w0b);
            fma8(accA, a.y, w1a, w1b);
            fma8(accB, b.x, w0a, w0b);
            fma8(accB, b.y, w1a, w1b);
        }

        const float4 u0 = *(const float4*)(w2s + mod * HH);
        const float4 u1 = *(const float4*)(w2s + mod * HH + 4);
        const float  bb = b2s[mod];
        float vA = bb, vB = bb;
        {
            const float* u = (const float*)&u0;
            const float* v = (const float*)&u1;
#pragma unroll
            for (int h = 0; h < 4; h++) {
                vA += tshrink(accA[h])     * u[h];
                vA += tshrink(accA[h + 4]) * v[h];
                vB += tshrink(accB[h])     * u[h];
                vB += tshrink(accB[h + 4]) * v[h];
            }
        }
        const float mA = tshrink(vA);
        const float mB = tshrink(vB);
        ms[mod * (TB + 1) + cA] = mA;
        ms[mod * (TB + 1) + cB] = mB;
        __syncthreads();

        // ---- write m coalesced: warp covers 4 cells x 8 mods = full 32B sectors ----
#pragma unroll
        for (int i = tid; i < TB * MC; i += NT) {
            const int cell = i >> 3;
            const int mo   = i & 7;
            out_m[(size_t)(cellBase + cell) * MM + modBase + mo] = ms[mo * (TB + 1) + cell];
        }

        // ---- accumulate c partials in registers ----
        float mv[MC];
#pragma unroll
        for (int mo = 0; mo < MC; mo++) mv[mo] = ms[mo * (TB + 1) + ccell];
#pragma unroll
        for (int j = 0; j < 18; j++) {
            const int comp = cset * 18 + j;
            if (comp < CC) {
                float s = 0.f;
#pragma unroll
                for (int mo = 0; mo < MC; mo++) s += mv[mo] * cms[comp * MC + mo];
                cacc[j] += s;
            }
        }
        __syncthreads();   // protect xs/ms/cms before next chunk's staging
    }

    // ---- write c: stage in shared (reuse xs), then fully-contiguous store ----
    float* csb = xs;   // needs 32*70 = 2240 floats <= SZ_XS
#pragma unroll
    for (int j = 0; j < 18; j++) {
        const int comp = cset * 18 + j;
        if (comp < CC) csb[ccell * CC + comp] = cacc[j];
    }
    __syncthreads();
#pragma unroll
    for (int i = tid; i < TB * CC; i += NT) {
        out_c[(size_t)cellBase * CC + i] = csb[i];
    }
}

extern "C" void kernel_launch(void* const* d_in, const int* in_sizes, int n_in,
                              void* d_out, int out_size) {
    const float* x  = (const float*)d_in[0];
    const float* W1 = (const float*)d_in[1];
    const float* W2 = (const float*)d_in[2];
    const float* b2 = (const float*)d_in[3];
    const float* cm = (const float*)d_in[4];

    float* out_m = (float*)d_out;                       // [B, M] first
    float* out_c = (float*)d_out + (size_t)BB * MM;     // then [B, C]

    cudaFuncSetAttribute(flux_fused_kernel,
                         cudaFuncAttributeMaxDynamicSharedMemorySize, SMEM_BYTES);

    flux_fused_kernel<<<BB / TB, NT, SMEM_BYTES>>>(x, W1, W2, b2, cm, out_m, out_c);
}

// round 8
// speedup vs baseline: 1.4322x; 1.4322x over previous
#include <cuda_runtime.h>
#include <cstddef>
#include <cstdint>

#define BB 16384
#define MM 256
#define GG 50
#define HH 8
#define CC 70

#define TB 32              // cells per block
#define MC 4               // modules per chunk
#define NCH (MM / MC)      // 64 chunks
#define NT 128             // threads per block (4 warps = 4 modules)
#define XSW 202            // floats per cell row: 200 data + 2 pad (conflict-free LDS.64)

#define XS_BUF (TB * XSW)        // 6464 floats per buffer
#define W1_BUF (MC * GG * HH)    // 1600
#define W2_BUF (MC * HH)         // 32
#define CM_BUF (CC * MC)         // 280

// shared layout (floats); all 16B-aligned offsets
#define OFF_XS  0
#define OFF_W1  (OFF_XS + 2 * XS_BUF)          // 12928
#define OFF_W2  (OFF_W1 + 2 * W1_BUF)          // 16128
#define OFF_B2  (OFF_W2 + 2 * W2_BUF)          // 16192
#define OFF_CM  (OFF_B2 + 2 * MC)              // 16200
#define OFF_MS  (OFF_CM + 2 * CM_BUF)          // 16760
#define SMEM_FLOATS (OFF_MS + MC * TB)         // 16888
#define SMEM_BYTES  (SMEM_FLOATS * 4)          // 67552

__device__ __forceinline__ float tshrink(float v) { return v - tanhf(v); }

__device__ __forceinline__ void fma8(float acc[HH], float xv, float4 w0, float4 w1) {
    acc[0] += xv * w0.x; acc[1] += xv * w0.y; acc[2] += xv * w0.z; acc[3] += xv * w0.w;
    acc[4] += xv * w1.x; acc[5] += xv * w1.y; acc[6] += xv * w1.z; acc[7] += xv * w1.w;
}

__device__ __forceinline__ void cpa8(uint32_t dst, const void* src) {
    asm volatile("cp.async.ca.shared.global [%0], [%1], 8;" :: "r"(dst), "l"(src));
}
__device__ __forceinline__ void cpa16(uint32_t dst, const void* src) {
    asm volatile("cp.async.cg.shared.global [%0], [%1], 16;" :: "r"(dst), "l"(src));
}
__device__ __forceinline__ void cpa_commit() {
    asm volatile("cp.async.commit_group;");
}
__device__ __forceinline__ void cpa_wait1() {
    asm volatile("cp.async.wait_group 1;" ::: "memory");
}

// Issue all async copies for chunk `ch` into parity buffer `p`.
__device__ __forceinline__ void prefetch_chunk(
    int ch, int p, int tid, int cellBase,
    const float* __restrict__ x,  const float* __restrict__ W1,
    const float* __restrict__ W2, const float* __restrict__ b2,
    const float* __restrict__ cm, uint32_t sbase)
{
    const int modBase = ch * MC;
    // x tile: 32 cells x 100 float2, gmem-coalesced, smem-contiguous per cell
#pragma unroll
    for (int i = tid; i < TB * 100; i += NT) {
        const int cell = i / 100;
        const int c2   = i - cell * 100;
        cpa8(sbase + (uint32_t)((OFF_XS + p * XS_BUF + cell * XSW + c2 * 2) * 4),
             x + (size_t)(cellBase + cell) * (MM * GG) + (size_t)modBase * GG + c2 * 2);
    }
    // W1 chunk: 400 x 16B contiguous
#pragma unroll
    for (int i = tid; i < W1_BUF / 4; i += NT) {
        cpa16(sbase + (uint32_t)((OFF_W1 + p * W1_BUF + i * 4) * 4),
              W1 + (size_t)modBase * (GG * HH) + i * 4);
    }
    // cm chunk: 70 comps x 4 mods (16B each, modBase*4B multiple of 16)
    if (tid < CC)
        cpa16(sbase + (uint32_t)((OFF_CM + p * CM_BUF + tid * MC) * 4),
              cm + (size_t)tid * MM + modBase);
    // W2 chunk: 8 x 16B
    if (tid < W2_BUF / 4)
        cpa16(sbase + (uint32_t)((OFF_W2 + p * W2_BUF + tid * 4) * 4),
              W2 + (size_t)modBase * HH + tid * 4);
    // b2 chunk: 1 x 16B
    if (tid == 0)
        cpa16(sbase + (uint32_t)((OFF_B2 + p * MC) * 4), b2 + modBase);
}

__global__ void __launch_bounds__(NT, 3) flux_fused_kernel(
    const float* __restrict__ x,    // [B, M*G]
    const float* __restrict__ W1,   // [M, G, H]
    const float* __restrict__ W2,   // [M, H]
    const float* __restrict__ b2,   // [M]
    const float* __restrict__ cm,   // [C, M]
    float* __restrict__ out_m,      // [B, M]
    float* __restrict__ out_c)      // [B, C]
{
    extern __shared__ float sm[];
    const uint32_t sbase = (uint32_t)__cvta_generic_to_shared(sm);

    const int tid      = threadIdx.x;
    const int cellBase = blockIdx.x * TB;

    // compute mapping: warp = module, lane = cell  (full W1 broadcast, CF x loads)
    const int mod  = tid >> 5;          // 0..3
    const int cell = tid & 31;          // 0..31

    // c-phase mapping: lane = cell, warp = comp-set of 18
    const int ccell = tid & 31;
    const int cset  = tid >> 5;

    float cacc[18];
#pragma unroll
    for (int j = 0; j < 18; j++) cacc[j] = 0.f;

    // prime the pipeline
    prefetch_chunk(0, 0, tid, cellBase, x, W1, W2, b2, cm, sbase);
    cpa_commit();

    for (int ch = 0; ch < NCH; ch++) {
        const int p = ch & 1;
        if (ch + 1 < NCH)
            prefetch_chunk(ch + 1, p ^ 1, tid, cellBase, x, W1, W2, b2, cm, sbase);
        cpa_commit();          // commit (possibly empty) group -> wait 1 drains chunk ch
        cpa_wait1();
        __syncthreads();

        const float* xs  = sm + OFF_XS + p * XS_BUF;
        const float* w1s = sm + OFF_W1 + p * W1_BUF;
        const float* w2s = sm + OFF_W2 + p * W2_BUF;
        const float* b2s = sm + OFF_B2 + p * MC;
        const float* cms = sm + OFF_CM + p * CM_BUF;
        float*       ms  = sm + OFF_MS;

        // ---- per-thread: one (cell, module) pair, h[8] in registers ----
        float acc[HH];
#pragma unroll
        for (int h = 0; h < HH; h++) acc[h] = 0.f;

        const float*  xp = xs + cell * XSW + mod * GG;
        const float4* wv = (const float4*)(w1s + mod * (GG * HH));

#pragma unroll
        for (int g = 0; g < GG; g += 2) {
            float2 xv = *(const float2*)(xp + g);          // conflict-free LDS.64
            float4 wa0 = wv[2 * g + 0], wa1 = wv[2 * g + 1];   // warp-broadcast
            float4 wb0 = wv[2 * g + 2], wb1 = wv[2 * g + 3];
            fma8(acc, xv.x, wa0, wa1);
            fma8(acc, xv.y, wb0, wb1);
        }

        const float4 u0 = *(const float4*)(w2s + mod * HH);
        const float4 u1 = *(const float4*)(w2s + mod * HH + 4);
        float v = b2s[mod];
        {
            const float* u = (const float*)&u0;
            const float* w = (const float*)&u1;
#pragma unroll
            for (int h = 0; h < 4; h++) {
                v += tshrink(acc[h])     * u[h];
                v += tshrink(acc[h + 4]) * w[h];
            }
        }
        ms[mod * TB + cell] = tshrink(v);
        __syncthreads();

        // ---- write m (16B-contiguous per cell-row segment) ----
        {
            const int mo = tid & (MC - 1);
            const int cl = tid >> 2;
            out_m[(size_t)(cellBase + cl) * MM + ch * MC + mo] = ms[mo * TB + cl];
        }

        // ---- accumulate c partials in registers ----
        float mv[MC];
#pragma unroll
        for (int mo = 0; mo < MC; mo++) mv[mo] = ms[mo * TB + ccell];
#pragma unroll
        for (int j = 0; j < 18; j++) {
            const int comp = cset * 18 + j;
            if (comp < CC) {
                float s = 0.f;
#pragma unroll
                for (int mo = 0; mo < MC; mo++) s += mv[mo] * cms[comp * MC + mo];
                cacc[j] += s;
            }
        }
        __syncthreads();   // ms (and smem bufs) safe to reuse next iteration
    }

    // ---- write c: stage in shared (reuse xs region), contiguous store ----
    float* csb = sm + OFF_XS;    // needs 32*70 = 2240 floats, fits easily
#pragma unroll
    for (int j = 0; j < 18; j++) {
        const int comp = cset * 18 + j;
        if (comp < CC) csb[ccell * CC + comp] = cacc[j];
    }
    __syncthreads();
#pragma unroll
    for (int i = tid; i < TB * CC; i += NT) {
        out_c[(size_t)cellBase * CC + i] = csb[i];
    }
}

extern "C" void kernel_launch(void* const* d_in, const int* in_sizes, int n_in,
                              void* d_out, int out_size) {
    const float* x  = (const float*)d_in[0];
    const float* W1 = (const float*)d_in[1];
    const float* W2 = (const float*)d_in[2];
    const float* b2 = (const float*)d_in[3];
    const float* cm = (const float*)d_in[4];

    float* out_m = (float*)d_out;                       // [B, M] first
    float* out_c = (float*)d_out + (size_t)BB * MM;     // then [B, C]

    cudaFuncSetAttribute(flux_fused_kernel,
                         cudaFuncAttributeMaxDynamicSharedMemorySize, SMEM_BYTES);

    flux_fused_kernel<<<BB / TB, NT, SMEM_BYTES>>>(x, W1, W2, b2, cm, out_m, out_c);
}

// round 9
// speedup vs baseline: 1.7122x; 1.1955x over previous
#include <cuda_runtime.h>
#include <cstddef>
#include <cstdint>

#define BB 16384
#define MM 256
#define GG 50
#define HH 8
#define CC 70

#define TB 16              // cells per block
#define MC 4               // modules per chunk
#define NCH (MM / MC)      // 64 chunks
#define NT 64              // 2 warps; warp = 2 modules x 16 cells
#define XSW 202            // 200 data floats + 2 pad -> conflict-free LDS.64

// shared layout (floats); all offsets 16B-aligned
#define OFF_XS 0                 // 16*202 = 3232
#define OFF_W1 3232              // 4*50*8 = 1600
#define OFF_CM 4832              // 70*4   = 280
#define OFF_W2 5112              // 4*8    = 32
#define OFF_B2 5144              // 4
#define OFF_MS 5148              // 4*16   = 64
#define SMEM_FLOATS 5216         // ~20.9 KB static

__device__ __forceinline__ float tshrink(float v) { return v - tanhf(v); }

__device__ __forceinline__ void fma8(float acc[HH], float xv, float4 w0, float4 w1) {
    acc[0] += xv * w0.x; acc[1] += xv * w0.y; acc[2] += xv * w0.z; acc[3] += xv * w0.w;
    acc[4] += xv * w1.x; acc[5] += xv * w1.y; acc[6] += xv * w1.z; acc[7] += xv * w1.w;
}

__device__ __forceinline__ void cpa8(uint32_t dst, const void* src) {
    asm volatile("cp.async.ca.shared.global [%0], [%1], 8;" :: "r"(dst), "l"(src));
}
__device__ __forceinline__ void cpa16(uint32_t dst, const void* src) {
    asm volatile("cp.async.cg.shared.global [%0], [%1], 16;" :: "r"(dst), "l"(src));
}
__device__ __forceinline__ void cpa_commit() {
    asm volatile("cp.async.commit_group;");
}
__device__ __forceinline__ void cpa_wait0() {
    asm volatile("cp.async.wait_group 0;" ::: "memory");
}

__global__ void __launch_bounds__(NT, 8) flux_fused_kernel(
    const float* __restrict__ x,    // [B, M*G]
    const float* __restrict__ W1,   // [M, G, H]
    const float* __restrict__ W2,   // [M, H]
    const float* __restrict__ b2,   // [M]
    const float* __restrict__ cm,   // [C, M]
    float* __restrict__ out_m,      // [B, M]
    float* __restrict__ out_c)      // [B, C]
{
    __shared__ float smem[SMEM_FLOATS];
    const uint32_t sbase = (uint32_t)__cvta_generic_to_shared(smem);

    const int tid      = threadIdx.x;
    const int cellBase = blockIdx.x * TB;

    // compute mapping: warp covers 2 modules x 16 cells
    const int wid  = tid >> 5;
    const int lane = tid & 31;
    const int mod  = wid * 2 + (lane >> 4);   // 0..3
    const int cell = lane & 15;               // 0..15

    // c-phase mapping: 16 cells x 4 comp-sets of 18
    const int ccell = tid & 15;
    const int cset  = tid >> 4;               // 0..3

    // prefetch mapping for x: 4 threads per cell row
    const int pcell = tid >> 2;               // 0..15
    const int pc2   = tid & 3;                // float2-quad within row
    const float* xrow = x + (size_t)(cellBase + pcell) * (MM * GG);

    float cacc[18];
#pragma unroll
    for (int j = 0; j < 18; j++) cacc[j] = 0.f;

    for (int ch = 0; ch < NCH; ch++) {
        const int modBase = ch * MC;

        // ---- stage chunk (single-buffered; cross-block interleave hides latency) ----
        {
            const float* xsrc = xrow + modBase * GG;   // 200 contiguous floats
#pragma unroll
            for (int k = 0; k < 25; k++) {
                const int c2 = pc2 + k * 4;            // float2 index 0..99
                cpa8(sbase + (uint32_t)((OFF_XS + pcell * XSW + c2 * 2) * 4),
                     xsrc + c2 * 2);
            }
#pragma unroll
            for (int i = tid; i < (MC * GG * HH) / 4; i += NT)
                cpa16(sbase + (uint32_t)((OFF_W1 + i * 4) * 4),
                      W1 + (size_t)modBase * (GG * HH) + i * 4);
#pragma unroll
            for (int i = tid; i < CC; i += NT)
                cpa16(sbase + (uint32_t)((OFF_CM + i * MC) * 4),
                      cm + (size_t)i * MM + modBase);
            if (tid < (MC * HH) / 4)
                cpa16(sbase + (uint32_t)((OFF_W2 + tid * 4) * 4),
                      W2 + (size_t)modBase * HH + tid * 4);
            if (tid == 0)
                cpa16(sbase + (uint32_t)(OFF_B2 * 4), b2 + modBase);
            cpa_commit();
            cpa_wait0();
            __syncthreads();
        }

        const float* xs  = smem + OFF_XS;
        const float* w1s = smem + OFF_W1;
        const float* cms = smem + OFF_CM;
        const float* w2s = smem + OFF_W2;
        const float* b2s = smem + OFF_B2;
        float*       ms  = smem + OFF_MS;

        // ---- per-thread (cell, module): h[8] in regs ----
        float acc[HH];
#pragma unroll
        for (int h = 0; h < HH; h++) acc[h] = 0.f;

        const float*  xp = xs + cell * XSW + mod * GG;
        const float4* wv = (const float4*)(w1s + mod * (GG * HH));

#pragma unroll
        for (int g = 0; g < GG; g += 2) {
            float2 xv = *(const float2*)(xp + g);          // CF LDS.64
            float4 a0 = wv[2 * g + 0], a1 = wv[2 * g + 1]; // 2-addr broadcast
            float4 b0 = wv[2 * g + 2], b1 = wv[2 * g + 3];
            fma8(acc, xv.x, a0, a1);
            fma8(acc, xv.y, b0, b1);
        }

        const float4 u0 = *(const float4*)(w2s + mod * HH);
        const float4 u1 = *(const float4*)(w2s + mod * HH + 4);
        float v = b2s[mod];
        {
            const float* u = (const float*)&u0;
            const float* w = (const float*)&u1;
#pragma unroll
            for (int h = 0; h < 4; h++) {
                v += tshrink(acc[h])     * u[h];
                v += tshrink(acc[h + 4]) * w[h];
            }
        }
        ms[mod * TB + cell] = tshrink(v);
        __syncthreads();

        // ---- write m (16B-contiguous per cell segment) ----
        {
            const int cl = tid >> 2;
            const int mo = tid & 3;
            out_m[(size_t)(cellBase + cl) * MM + modBase + mo] = ms[mo * TB + cl];
        }

        // ---- accumulate c partials in registers ----
        float mv[MC];
#pragma unroll
        for (int mo = 0; mo < MC; mo++) mv[mo] = ms[mo * TB + ccell];
#pragma unroll
        for (int j = 0; j < 18; j++) {
            const int comp = cset * 18 + j;
            if (comp < CC) {
                float s = 0.f;
#pragma unroll
                for (int mo = 0; mo < MC; mo++) s += mv[mo] * cms[comp * MC + mo];
                cacc[j] += s;
            }
        }
        __syncthreads();   // all smem buffers free for next chunk's staging
    }

    // ---- write c: stage in shared (reuse xs region), contiguous store ----
    float* csb = smem + OFF_XS;   // needs 16*70 = 1120 floats
#pragma unroll
    for (int j = 0; j < 18; j++) {
        const int comp = cset * 18 + j;
        if (comp < CC) csb[ccell * CC + comp] = cacc[j];
    }
    __syncthreads();
#pragma unroll
    for (int i = tid; i < TB * CC; i += NT) {
        out_c[(size_t)cellBase * CC + i] = csb[i];
    }
}

extern "C" void kernel_launch(void* const* d_in, const int* in_sizes, int n_in,
                              void* d_out, int out_size) {
    const float* x  = (const float*)d_in[0];
    const float* W1 = (const float*)d_in[1];
    const float* W2 = (const float*)d_in[2];
    const float* b2 = (const float*)d_in[3];
    const float* cm = (const float*)d_in[4];

    float* out_m = (float*)d_out;                       // [B, M] first
    float* out_c = (float*)d_out + (size_t)BB * MM;     // then [B, C]

    flux_fused_kernel<<<BB / TB, NT>>>(x, W1, W2, b2, cm, out_m, out_c);
}